// round 7
// baseline (speedup 1.0000x reference)
#include <cuda_runtime.h>

// FoldNd (col2im): B=16, C=64, K=3, H=W=128, PAD=1, STR=1, DIL=1
// Gather form, vec4 per thread-iteration, warp = one output row, boundary
// elements via warp shuffle. Persistent grid-stride: one resident wave
// (148 SMs x 2 CTAs x 512 thr), no CTA launch/drain between tiles.
// Input read-once -> __ldcs; output write-once -> __stcs.

namespace {
constexpr int H = 128;
constexpr int W = 128;
constexpr int PLANE = H * W;            // 16384
constexpr int NOUT = 16 * 64 * H * W;   // 16,777,216
constexpr int NVEC = NOUT / 4;          // 4,194,304
constexpr int NBLOCKS = 296;            // 148 SMs * 2 resident CTAs
constexpr int NTHREADS = 512;
}

__global__ void __launch_bounds__(NTHREADS) fold_vec4_persist_kernel(
    const float* __restrict__ in, float* __restrict__ out)
{
    const int stride = NBLOCKS * NTHREADS;           // 151,552
    int lane = threadIdx.x & 31;
    int w0 = lane << 2;                              // constant per thread: 0..124

    for (int v = blockIdx.x * NTHREADS + threadIdx.x; v < NVEC; v += stride) {
        int h  = (v >> 5) & (H - 1);
        int bc = v >> 12;                            // b*64 + c

        const float* base = in + (long long)bc * 9 * PLANE;

        float4 acc = make_float4(0.f, 0.f, 0.f, 0.f);

        #pragma unroll
        for (int kh = 0; kh < 3; ++kh) {
            int lh = h + 1 - kh;                     // warp-uniform predicate
            if ((unsigned)lh < (unsigned)H) {
                const float* r0 = base + (kh * 3 + 0) * PLANE + lh * W; // kw=0
                const float* r1 = r0 + PLANE;                            // kw=1
                const float* r2 = r1 + PLANE;                            // kw=2

                float4 A  = __ldcs(reinterpret_cast<const float4*>(r0 + w0));
                float4 Bv = __ldcs(reinterpret_cast<const float4*>(r1 + w0));
                float4 Cv = __ldcs(reinterpret_cast<const float4*>(r2 + w0));

                // a4  = r0[w0+4] = next lane's A.x   (lane 31: lw=128 -> 0)
                // cm1 = r2[w0-1] = prev lane's Cv.w  (lane 0:  lw=-1  -> 0)
                float a4  = __shfl_down_sync(0xFFFFFFFFu, A.x, 1);
                float cm1 = __shfl_up_sync(0xFFFFFFFFu, Cv.w, 1);
                if (lane == 31) a4  = 0.f;
                if (lane == 0)  cm1 = 0.f;

                // output w0+j: kw0 -> elem(w0+j+1), kw1 -> elem(w0+j),
                //              kw2 -> elem(w0+j-1)
                acc.x += A.y + Bv.x + cm1;
                acc.y += A.z + Bv.y + Cv.x;
                acc.z += A.w + Bv.z + Cv.y;
                acc.w += a4  + Bv.w + Cv.z;
            }
        }

        __stcs(reinterpret_cast<float4*>(out) + v, acc);
    }
}

extern "C" void kernel_launch(void* const* d_in, const int* in_sizes, int n_in,
                              void* d_out, int out_size)
{
    const float* in = (const float*)d_in[0];
    float* out = (float*)d_out;
    fold_vec4_persist_kernel<<<NBLOCKS, NTHREADS>>>(in, out);
}

// round 8
// speedup vs baseline: 1.0335x; 1.0335x over previous
#include <cuda_runtime.h>

// FoldNd (col2im): B=16, C=64, K=3, H=W=128, PAD=1, STR=1, DIL=1
// Gather form, vec4 per iteration, warp = one output row, boundary elements
// via warp shuffle. Persistent grid-stride at FULL occupancy:
// 592 blocks = 148 SMs x 4 CTAs x 512 thr = 2048 thr/SM (64 warps),
// __launch_bounds__(512,4) caps regs at 32 so all 4 CTAs are resident.
// Input read-once -> __ldcs; output write-once -> __stcs.

namespace {
constexpr int H = 128;
constexpr int W = 128;
constexpr int PLANE = H * W;            // 16384
constexpr int NOUT = 16 * 64 * H * W;   // 16,777,216
constexpr int NVEC = NOUT / 4;          // 4,194,304
constexpr int NBLOCKS = 592;            // 148 SMs * 4 resident CTAs
constexpr int NTHREADS = 512;
}

__global__ void __launch_bounds__(NTHREADS, 4) fold_vec4_persist4_kernel(
    const float* __restrict__ in, float* __restrict__ out)
{
    const int stride = NBLOCKS * NTHREADS;           // 303,104
    int lane = threadIdx.x & 31;
    int w0 = lane << 2;                              // constant per thread: 0..124

    for (int v = blockIdx.x * NTHREADS + threadIdx.x; v < NVEC; v += stride) {
        int h  = (v >> 5) & (H - 1);
        int bc = v >> 12;                            // b*64 + c

        const float* base = in + (long long)bc * 9 * PLANE;

        float4 acc = make_float4(0.f, 0.f, 0.f, 0.f);

        #pragma unroll
        for (int kh = 0; kh < 3; ++kh) {
            int lh = h + 1 - kh;                     // warp-uniform predicate
            if ((unsigned)lh < (unsigned)H) {
                const float* r0 = base + (kh * 3 + 0) * PLANE + lh * W; // kw=0
                const float* r1 = r0 + PLANE;                            // kw=1
                const float* r2 = r1 + PLANE;                            // kw=2

                float4 A  = __ldcs(reinterpret_cast<const float4*>(r0 + w0));
                float4 Bv = __ldcs(reinterpret_cast<const float4*>(r1 + w0));
                float4 Cv = __ldcs(reinterpret_cast<const float4*>(r2 + w0));

                // a4  = r0[w0+4] = next lane's A.x   (lane 31: lw=128 -> 0)
                // cm1 = r2[w0-1] = prev lane's Cv.w  (lane 0:  lw=-1  -> 0)
                float a4  = __shfl_down_sync(0xFFFFFFFFu, A.x, 1);
                float cm1 = __shfl_up_sync(0xFFFFFFFFu, Cv.w, 1);
                if (lane == 31) a4  = 0.f;
                if (lane == 0)  cm1 = 0.f;

                // output w0+j: kw0 -> elem(w0+j+1), kw1 -> elem(w0+j),
                //              kw2 -> elem(w0+j-1)
                acc.x += A.y + Bv.x + cm1;
                acc.y += A.z + Bv.y + Cv.x;
                acc.z += A.w + Bv.z + Cv.y;
                acc.w += a4  + Bv.w + Cv.z;
            }
        }

        __stcs(reinterpret_cast<float4*>(out) + v, acc);
    }
}

extern "C" void kernel_launch(void* const* d_in, const int* in_sizes, int n_in,
                              void* d_out, int out_size)
{
    const float* in = (const float*)d_in[0];
    float* out = (float*)d_out;
    fold_vec4_persist4_kernel<<<NBLOCKS, NTHREADS>>>(in, out);
}

// round 9
// speedup vs baseline: 1.0731x; 1.0384x over previous
#include <cuda_runtime.h>

// FoldNd (col2im): B=16, C=64, K=3, H=W=128, PAD=1, STR=1, DIL=1
// FINAL (converged at memory ceiling, ~7.0 TB/s through L2/DRAM):
// Gather form, vec4 per thread, warp = one output row (32 lanes x 4 px),
// boundary elements (lw = w0-1, w0+4) exchanged via warp shuffle -> exactly
// 9 aligned LDG.128 + 1 STG.128 per thread, zero scalar loads.
// Input is read-once streaming -> __ldcs; output write-once -> __stcs.
// Plain grid (8192 x 512): beats persistent variants — fresh CTAs issue
// their load batch with no loop-carried dependency.

namespace {
constexpr int H = 128;
constexpr int W = 128;
constexpr int PLANE = H * W;            // 16384
constexpr int NOUT = 16 * 64 * H * W;   // 16,777,216
constexpr int NVEC = NOUT / 4;          // 4,194,304
}

__global__ void __launch_bounds__(512) fold_vec4_stream_kernel(
    const float* __restrict__ in, float* __restrict__ out)
{
    int v = blockIdx.x * blockDim.x + threadIdx.x;   // grid covers NVEC exactly

    int lane = v & 31;
    int w0 = lane << 2;              // 0,4,...,124 (warp spans one row)
    int h  = (v >> 5) & (H - 1);
    int bc = v >> 12;                // b*64 + c

    const float* base = in + (long long)bc * 9 * PLANE;

    float4 acc = make_float4(0.f, 0.f, 0.f, 0.f);

    #pragma unroll
    for (int kh = 0; kh < 3; ++kh) {
        int lh = h + 1 - kh;         // warp-uniform predicate
        if ((unsigned)lh < (unsigned)H) {
            const float* r0 = base + (kh * 3 + 0) * PLANE + lh * W; // kw=0
            const float* r1 = r0 + PLANE;                            // kw=1
            const float* r2 = r1 + PLANE;                            // kw=2

            float4 A  = __ldcs(reinterpret_cast<const float4*>(r0 + w0));
            float4 Bv = __ldcs(reinterpret_cast<const float4*>(r1 + w0));
            float4 Cv = __ldcs(reinterpret_cast<const float4*>(r2 + w0));

            // a4  = r0[w0+4] = next lane's A.x   (lane 31: lw=128 -> 0)
            // cm1 = r2[w0-1] = prev lane's Cv.w  (lane 0:  lw=-1  -> 0)
            float a4  = __shfl_down_sync(0xFFFFFFFFu, A.x, 1);
            float cm1 = __shfl_up_sync(0xFFFFFFFFu, Cv.w, 1);
            if (lane == 31) a4  = 0.f;
            if (lane == 0)  cm1 = 0.f;

            // output w0+j: kw0 -> elem(w0+j+1), kw1 -> elem(w0+j), kw2 -> elem(w0+j-1)
            acc.x += A.y + Bv.x + cm1;
            acc.y += A.z + Bv.y + Cv.x;
            acc.z += A.w + Bv.z + Cv.y;
            acc.w += a4  + Bv.w + Cv.z;
        }
    }

    __stcs(reinterpret_cast<float4*>(out) + v, acc);
}

extern "C" void kernel_launch(void* const* d_in, const int* in_sizes, int n_in,
                              void* d_out, int out_size)
{
    const float* in = (const float*)d_in[0];
    float* out = (float*)d_out;
    const int threads = 512;
    const int blocks = NVEC / threads;   // exact: 8192 blocks
    fold_vec4_stream_kernel<<<blocks, threads>>>(in, out);
}

// round 10
// speedup vs baseline: 1.0742x; 1.0010x over previous
#include <cuda_runtime.h>

// FoldNd (col2im): B=16, C=64, K=3, H=W=128, PAD=1, STR=1, DIL=1
// FINAL — converged at the memory-fabric ceiling.
//   traffic floor: 604 MB read (once) + 67 MB write (once) = 671 MB
//   chip cap:      ~6.95 TB/s through LTS/DRAM (path-independent)
//   => 96 us floor; this kernel measures 96.0-96.7 us (noise band).
//
// Structure: gather form (no atomics), one float4 of output per thread,
// warp = one 128-wide output row, so the +/-1 halo elements come from
// neighbor lanes via warp shuffle -> exactly 9 aligned LDG.128 + 1 STG.128
// per thread, zero scalar loads, zero misaligned wavefronts.
// Read-once input  -> __ldcs (evict-first), write-once output -> __stcs.
// Plain grid (8192 x 512) beats persistent variants: fresh CTAs issue their
// full load batch with no loop-carried dependency (verified R7/R8).

namespace {
constexpr int H = 128;
constexpr int W = 128;
constexpr int PLANE = H * W;            // 16384
constexpr int NOUT = 16 * 64 * H * W;   // 16,777,216
constexpr int NVEC = NOUT / 4;          // 4,194,304
}

__global__ void __launch_bounds__(512) fold_vec4_stream_kernel(
    const float* __restrict__ in, float* __restrict__ out)
{
    int v = blockIdx.x * blockDim.x + threadIdx.x;   // grid covers NVEC exactly

    int lane = v & 31;
    int w0 = lane << 2;              // 0,4,...,124 (warp spans one row)
    int h  = (v >> 5) & (H - 1);
    int bc = v >> 12;                // b*64 + c

    const float* base = in + (long long)bc * 9 * PLANE;

    float4 acc = make_float4(0.f, 0.f, 0.f, 0.f);

    #pragma unroll
    for (int kh = 0; kh < 3; ++kh) {
        int lh = h + 1 - kh;         // warp-uniform predicate
        if ((unsigned)lh < (unsigned)H) {
            const float* r0 = base + (kh * 3 + 0) * PLANE + lh * W; // kw=0
            const float* r1 = r0 + PLANE;                            // kw=1
            const float* r2 = r1 + PLANE;                            // kw=2

            float4 A  = __ldcs(reinterpret_cast<const float4*>(r0 + w0));
            float4 Bv = __ldcs(reinterpret_cast<const float4*>(r1 + w0));
            float4 Cv = __ldcs(reinterpret_cast<const float4*>(r2 + w0));

            // a4  = r0[w0+4] = next lane's A.x   (lane 31: lw=128 -> 0)
            // cm1 = r2[w0-1] = prev lane's Cv.w  (lane 0:  lw=-1  -> 0)
            float a4  = __shfl_down_sync(0xFFFFFFFFu, A.x, 1);
            float cm1 = __shfl_up_sync(0xFFFFFFFFu, Cv.w, 1);
            if (lane == 31) a4  = 0.f;
            if (lane == 0)  cm1 = 0.f;

            // output w0+j: kw0 -> elem(w0+j+1), kw1 -> elem(w0+j), kw2 -> elem(w0+j-1)
            acc.x += A.y + Bv.x + cm1;
            acc.y += A.z + Bv.y + Cv.x;
            acc.z += A.w + Bv.z + Cv.y;
            acc.w += a4  + Bv.w + Cv.z;
        }
    }

    __stcs(reinterpret_cast<float4*>(out) + v, acc);
}

extern "C" void kernel_launch(void* const* d_in, const int* in_sizes, int n_in,
                              void* d_out, int out_size)
{
    const float* in = (const float*)d_in[0];
    float* out = (float*)d_out;
    const int threads = 512;
    const int blocks = NVEC / threads;   // exact: 8192 blocks
    fold_vec4_stream_kernel<<<blocks, threads>>>(in, out);
}